// round 4
// baseline (speedup 1.0000x reference)
#include <cuda_runtime.h>

// Problem constants (N_ATOMS = 128, fixed by the reference)
#define NA      128
#define NSEG    7875          // sum_{i=0}^{124} (125 - i)
#define OUTPB   16256         // n^2 - n  (all off-diagonal cells, row-major)
#define NQUADS  4064          // OUTPB / 4
#define THREADS 256
#define CHUNK   31            // ceil(NSEG / THREADS)

// off(i) = number of segments with first index < i  (n = 128)
__device__ __forceinline__ int seg_off(int i) { return (i * (251 - i)) >> 1; }

// Branch-free asin via Abramowitz & Stegun 4.4.46 (|eps| ~ 1e-7 in float)
__device__ __forceinline__ float fast_asin(float x)
{
    const float a = fabsf(x);
    float p = fmaf(a, -0.0012624911f, 0.0066700901f);
    p = fmaf(a, p, -0.0170881256f);
    p = fmaf(a, p,  0.0308918810f);
    p = fmaf(a, p, -0.0501743046f);
    p = fmaf(a, p,  0.0889789874f);
    p = fmaf(a, p, -0.2145988016f);
    p = fmaf(a, p,  1.5707963050f);
    const float om = 1.0f - a;                       // >= 0 (input clamped)
    const float s  = om * rsqrtf(fmaxf(om, 1e-38f)); // sqrt(om) via MUFU
    return copysignf(1.5707963268f - s * p, x);
}

// Triangle lookup with validity predicate: wr(min,max) or 0
__device__ __forceinline__ float look(const float* __restrict__ sh, int u, int v)
{
    const int x = min(u, v), y = max(u, v);
    const bool ok = (x >= 0) & (y <= 126) & ((y - x) >= 2);
    return ok ? sh[seg_off(x) + y - x - 2] : 0.0f;
}

// -------------------------------------------------------------------------
// Fused kernel: one block per batch.
// Phase 1: all 7875 segment writhes -> shared triangle (with j-chain carries).
// Phase 2: 2x2 symmetric stencil with intra-quad tap reuse -> float4 stores.
// -------------------------------------------------------------------------
__global__ __launch_bounds__(THREADS, 4) void fused_kernel(const float* __restrict__ xyz,
                                                           float* __restrict__ out)
{
    __shared__ float4 pt[NA];
    __shared__ float  sh_wr[NSEG];

    const int b   = blockIdx.x;
    const int tid = threadIdx.x;

    const float* x = xyz + (size_t)b * NA * 3;
    for (int t = tid; t < NA; t += THREADS)
        pt[t] = make_float4(x[3 * t + 0], x[3 * t + 1], x[3 * t + 2], 0.0f);
    __syncthreads();

    // ---- Phase 1 ----
    const int s0   = tid * CHUNK;
    const int send = min(s0 + CHUNK, NSEG);

    if (s0 < NSEG) {
        // invert s0 -> (i, j) once
        int i = (int)((251.0f - sqrtf(63001.0f - 8.0f * (float)s0)) * 0.5f);
        if (i < 0) i = 0;
        if (i > 124) i = 124;
        while (i < 124 && seg_off(i + 1) <= s0) i++;
        while (i > 0 && seg_off(i) > s0) i--;
        int j = s0 - seg_off(i) + i + 2;
        int s = s0;

        while (s < send) {
            const float4 P0 = pt[i];
            const float4 P1 = pt[i + 1];
            const float4 P2 = pt[j];

            // carried state for this row
            float d0x = P2.x - P0.x, d0y = P2.y - P0.y, d0z = P2.z - P0.z;
            float d2x = P2.x - P1.x, d2y = P2.y - P1.y, d2z = P2.z - P1.z;
            // c3 = d2 x d0
            float c3x = d2y * d0z - d2z * d0y;
            float c3y = d2z * d0x - d2x * d0z;
            float c3z = d2x * d0y - d2y * d0x;
            float r3  = rsqrtf(c3x * c3x + c3y * c3y + c3z * c3z);

            for (; j <= 126 && s < send; ++j, ++s) {
                const float4 P3 = pt[j + 1];
                const float d1x = P3.x - P0.x, d1y = P3.y - P0.y, d1z = P3.z - P0.z;
                const float d3x = P3.x - P1.x, d3y = P3.y - P1.y, d3z = P3.z - P1.z;

                // c0 = d0 x d1, c1 = d1 x d3, c2 = d3 x d2
                const float c0x = d0y * d1z - d0z * d1y;
                const float c0y = d0z * d1x - d0x * d1z;
                const float c0z = d0x * d1y - d0y * d1x;

                const float c1x = d1y * d3z - d1z * d3y;
                const float c1y = d1z * d3x - d1x * d3z;
                const float c1z = d1x * d3y - d1y * d3x;

                const float c2x = d3y * d2z - d3z * d2y;
                const float c2y = d3z * d2x - d3x * d2z;
                const float c2z = d3x * d2y - d3y * d2x;

                // sign: axial . d0 == -det[d0,d1,d2] == -(d2 . c0)
                const float dp = -(d2x * c0x + d2y * c0y + d2z * c0z);
                const float sg = (dp > 0.0f) ? 1.0f : ((dp < 0.0f) ? -1.0f : 0.0f);

                const float r0 = rsqrtf(c0x * c0x + c0y * c0y + c0z * c0z);
                const float r1 = rsqrtf(c1x * c1x + c1y * c1y + c1z * c1z);
                const float r2 = rsqrtf(c2x * c2x + c2y * c2y + c2z * c2z);

                float q0 = (c0x * c1x + c0y * c1y + c0z * c1z) * r0 * r1;
                float q1 = (c1x * c2x + c1y * c2y + c1z * c2z) * r1 * r2;
                float q2 = (c2x * c3x + c2y * c3y + c2z * c3z) * r2 * r3;
                float q3 = (c3x * c0x + c3y * c0y + c3z * c0z) * r3 * r0;

                q0 = fminf(fmaxf(q0, -1.0f), 1.0f);
                q1 = fminf(fmaxf(q1, -1.0f), 1.0f);
                q2 = fminf(fmaxf(q2, -1.0f), 1.0f);
                q3 = fminf(fmaxf(q3, -1.0f), 1.0f);

                const float omega = fast_asin(q0) + fast_asin(q1) +
                                    fast_asin(q2) + fast_asin(q3);

                sh_wr[s] = omega * sg * 0.15915494309189535f; // 1/(2*pi)

                // carry to j+1: d0 <- d1, d2 <- d3, c3 <- -c1, r3 <- r1
                d0x = d1x; d0y = d1y; d0z = d1z;
                d2x = d3x; d2y = d3y; d2z = d3z;
                c3x = -c1x; c3y = -c1y; c3z = -c1z;
                r3  = r1;
            }
            ++i;
            j = i + 2;
        }
    }
    __syncthreads();

    // ---- Phase 2: stencil gather with intra-quad tap reuse ----
    float4* outq = (float4*)(out + (size_t)b * OUTPB);

    // incremental (row, col') state for k = 4*tid, advancing by 1024 per iter
    int r  = (4 * tid) / 127;
    int cp = 4 * tid - r * 127;

    for (int it = 0; it < 16; ++it) {
        const int q = tid + it * THREADS;
        if (q < NQUADS) {
            float v[4];
            float prevA = 0.0f, prevB = 0.0f;
            int   pr = -9, pc = -9;
            #pragma unroll
            for (int m = 0; m < 4; ++m) {
                int cpm = cp + m, rm = r;
                if (cpm >= 127) { cpm -= 127; rm += 1; }
                const int cm = cpm + (cpm >= rm ? 1 : 0);

                float la, lb;
                if (rm == pr && cm == pc + 1) {
                    la = prevA; lb = prevB;           // taps shared with prev element
                } else {
                    la = look(sh_wr, rm, cm - 1);
                    lb = look(sh_wr, rm - 1, cm - 1);
                }
                const float a  = look(sh_wr, rm, cm);
                const float bb = look(sh_wr, rm - 1, cm);
                v[m] = a + bb + la + lb;
                prevA = a; prevB = bb; pr = rm; pc = cm;
            }
            outq[q] = make_float4(v[0], v[1], v[2], v[3]);
        }
        // advance by 1024 output elements: +8 rows, +8 cols (one extra wrap max)
        r += 8; cp += 8;
        if (cp >= 127) { cp -= 127; r += 1; }
    }
}

// -------------------------------------------------------------------------
extern "C" void kernel_launch(void* const* d_in, const int* in_sizes, int n_in,
                              void* d_out, int out_size)
{
    const float* xyz = (const float*)d_in[0];
    const int B = in_sizes[0] / (NA * 3);

    fused_kernel<<<B, THREADS>>>(xyz, (float*)d_out);
}

// round 5
// speedup vs baseline: 1.4880x; 1.4880x over previous
#include <cuda_runtime.h>

// Problem constants (N_ATOMS = 128, fixed by the reference)
#define NA      128
#define NSEG    7875          // sum_{i=0}^{124} (125 - i)
#define OUTPB   16256         // n^2 - n  (all off-diagonal cells, row-major)
#define NQUADS  4064          // OUTPB / 4
#define MAXB    512
#define SDIM    130           // padded symmetric matrix, zero border

// Scratch: per-batch padded symmetric segment-writhe matrix (~34.6 MB).
// Zero-initialized at module load; invalid entries are NEVER written, so the
// zero border / zero invalid cells are permanent and deterministic.
__device__ float g_S[(size_t)MAXB * SDIM * SDIM];

// off(i) = number of segments with first index < i  (n = 128)
__device__ __forceinline__ int seg_off(int i) { return (i * (251 - i)) >> 1; }

// Branch-free asin via Abramowitz & Stegun 4.4.46 (|eps| ~ 1e-7 in float)
__device__ __forceinline__ float fast_asin(float x)
{
    const float a = fabsf(x);
    float p = fmaf(a, -0.0012624911f, 0.0066700901f);
    p = fmaf(a, p, -0.0170881256f);
    p = fmaf(a, p,  0.0308918810f);
    p = fmaf(a, p, -0.0501743046f);
    p = fmaf(a, p,  0.0889789874f);
    p = fmaf(a, p, -0.2145988016f);
    p = fmaf(a, p,  1.5707963050f);
    const float om = 1.0f - a;                       // >= 0 (input clamped)
    const float s  = om * rsqrtf(fmaxf(om, 1e-38f)); // sqrt(om) via MUFU
    return copysignf(1.5707963268f - s * p, x);
}

// -------------------------------------------------------------------------
// Kernel 1: writhe per (batch, segment); store symmetric into padded S.
// One segment per thread, branch-free body, full machine occupancy.
// -------------------------------------------------------------------------
__global__ __launch_bounds__(256) void writhe_kernel(const float* __restrict__ xyz)
{
    __shared__ float4 pt[NA];
    const int b = blockIdx.y;
    const float* x = xyz + (size_t)b * NA * 3;
    for (int t = threadIdx.x; t < NA; t += blockDim.x)
        pt[t] = make_float4(x[3 * t + 0], x[3 * t + 1], x[3 * t + 2], 0.0f);
    __syncthreads();

    const int s = blockIdx.x * blockDim.x + threadIdx.x;
    if (s >= NSEG) return;

    // invert s -> (i, j):  largest i with seg_off(i) <= s
    int i = (int)((251.0f - sqrtf(63001.0f - 8.0f * (float)s)) * 0.5f);
    if (i < 0) i = 0;
    if (i > 124) i = 124;
    while (i < 124 && seg_off(i + 1) <= s) i++;
    while (i > 0 && seg_off(i) > s) i--;
    const int j = s - seg_off(i) + i + 2;

    const float4 P0 = pt[i];
    const float4 P1 = pt[i + 1];
    const float4 P2 = pt[j];
    const float4 P3 = pt[j + 1];

    // unnormalized directions (normalization is redundant)
    const float d0x = P2.x - P0.x, d0y = P2.y - P0.y, d0z = P2.z - P0.z;
    const float d1x = P3.x - P0.x, d1y = P3.y - P0.y, d1z = P3.z - P0.z;
    const float d2x = P2.x - P1.x, d2y = P2.y - P1.y, d2z = P2.z - P1.z;
    const float d3x = P3.x - P1.x, d3y = P3.y - P1.y, d3z = P3.z - P1.z;

    // c0 = d0 x d1, c1 = d1 x d3, c2 = d3 x d2, c3 = d2 x d0
    const float c0x = d0y * d1z - d0z * d1y;
    const float c0y = d0z * d1x - d0x * d1z;
    const float c0z = d0x * d1y - d0y * d1x;

    const float c1x = d1y * d3z - d1z * d3y;
    const float c1y = d1z * d3x - d1x * d3z;
    const float c1z = d1x * d3y - d1y * d3x;

    const float c2x = d3y * d2z - d3z * d2y;
    const float c2y = d3z * d2x - d3x * d2z;
    const float c2z = d3x * d2y - d3y * d2x;

    const float c3x = d2y * d0z - d2z * d0y;
    const float c3y = d2z * d0x - d2x * d0z;
    const float c3z = d2x * d0y - d2y * d0x;

    // sign: dot(axial, d0) == -det[d0, d1, d2] == -(d2 . c0)
    const float dp = -(d2x * c0x + d2y * c0y + d2z * c0z);
    const float sg = (dp > 0.0f) ? 1.0f : ((dp < 0.0f) ? -1.0f : 0.0f);

    const float r0 = rsqrtf(c0x * c0x + c0y * c0y + c0z * c0z);
    const float r1 = rsqrtf(c1x * c1x + c1y * c1y + c1z * c1z);
    const float r2 = rsqrtf(c2x * c2x + c2y * c2y + c2z * c2z);
    const float r3 = rsqrtf(c3x * c3x + c3y * c3y + c3z * c3z);

    float q0 = (c0x * c1x + c0y * c1y + c0z * c1z) * r0 * r1;
    float q1 = (c1x * c2x + c1y * c2y + c1z * c2z) * r1 * r2;
    float q2 = (c2x * c3x + c2y * c3y + c2z * c3z) * r2 * r3;
    float q3 = (c3x * c0x + c3y * c0y + c3z * c0z) * r3 * r0;

    q0 = fminf(fmaxf(q0, -1.0f), 1.0f);
    q1 = fminf(fmaxf(q1, -1.0f), 1.0f);
    q2 = fminf(fmaxf(q2, -1.0f), 1.0f);
    q3 = fminf(fmaxf(q3, -1.0f), 1.0f);

    const float omega = fast_asin(q0) + fast_asin(q1) +
                        fast_asin(q2) + fast_asin(q3);
    const float wr = omega * sg * 0.15915494309189535f; // 1/(2*pi)

    float* S = g_S + (size_t)b * SDIM * SDIM;
    S[(i + 1) * SDIM + (j + 1)] = wr;   // coalesced
    S[(j + 1) * SDIM + (i + 1)] = wr;   // transposed (absorbed by L2)
}

// -------------------------------------------------------------------------
// Kernel 2: streaming 2x2 stencil, float4 stores (4 outputs per thread).
// out[b, k], k <-> (r, c) row-major off-diagonal:
//   out = S[r][c] + S[r][c-1] + S[r-1][c] + S[r-1][c-1]  (padded coords +1)
// -------------------------------------------------------------------------
__global__ __launch_bounds__(256) void gather_kernel(float* __restrict__ out)
{
    const int q = blockIdx.x * blockDim.x + threadIdx.x;
    const int b = blockIdx.y;
    if (q >= NQUADS) return;

    const float* S = g_S + (size_t)b * SDIM * SDIM;

    float v[4];
    #pragma unroll
    for (int m = 0; m < 4; ++m) {
        const int k  = 4 * q + m;
        const int r  = k / 127;
        const int cp = k - r * 127;
        const int c  = cp + (cp >= r ? 1 : 0);
        const float* row1 = S + (r + 1) * SDIM;
        const float* row0 = S + r * SDIM;
        v[m] = row1[c + 1] + row1[c] + row0[c + 1] + row0[c];
    }

    float4* outq = (float4*)(out + (size_t)b * OUTPB);
    outq[q] = make_float4(v[0], v[1], v[2], v[3]);
}

// -------------------------------------------------------------------------
extern "C" void kernel_launch(void* const* d_in, const int* in_sizes, int n_in,
                              void* d_out, int out_size)
{
    const float* xyz = (const float*)d_in[0];
    int B = in_sizes[0] / (NA * 3);
    if (B > MAXB) B = MAXB;

    dim3 gw((NSEG + 255) / 256, B);
    writhe_kernel<<<gw, 256>>>(xyz);

    dim3 gg((NQUADS + 255) / 256, B);
    gather_kernel<<<gg, 256>>>((float*)d_out);
}